// round 1
// baseline (speedup 1.0000x reference)
#include <cuda_runtime.h>
#include <math.h>

// ---------------------------------------------------------------------------
// SE4: 4x4-patch squeeze-excite
//   t: [B=8, C=64, H=256, W=256] fp32
//   pooled[b, (i*4+j)*64 + c] = mean of 64x64 patch (i,j) of channel c
//   s = mish(pooled @ reduce_w^T + reduce_b)   [8,256]
//   g = sigmoid(s @ expand_w^T + expand_b)     [8,1024]
//   out[b,c,h,w] = t[b,c,h,w] * g[b, (h/64*4 + w/64)*64 + c]
// ---------------------------------------------------------------------------

#define B_   8
#define C_   64
#define H_   256
#define W_   256
#define SQ_  256
#define GC_  (16 * C_)          // 1024
#define NPOOL (B_ * GC_)        // 8192

__device__ float g_pooled[NPOOL];
__device__ float g_gates[NPOOL];

// ---------------------------------------------------------------------------
// Kernel 1: patch mean pool. One warp per (b, c, i, j). 8192 warps total.
// Each lane: col4 = lane%16 (16 float4 = 64 floats per row), row = 2*iter + lane/16
// ---------------------------------------------------------------------------
__global__ void __launch_bounds__(256) se4_pool(const float* __restrict__ t) {
    int warp = (blockIdx.x * blockDim.x + threadIdx.x) >> 5;
    int lane = threadIdx.x & 31;
    if (warp >= NPOOL) return;

    int b  = warp >> 10;            // / 1024
    int r  = warp & 1023;
    int c  = r >> 4;                // / 16
    int ij = r & 15;
    int i  = ij >> 2;
    int j  = ij & 3;

    const float* base = t + (((size_t)(b * C_ + c) * H_ + i * 64) * W_ + j * 64);
    int row0 = lane >> 4;           // 0 or 1
    int col4 = lane & 15;           // 0..15

    float acc = 0.0f;
#pragma unroll 8
    for (int it = 0; it < 32; ++it) {
        int row = it * 2 + row0;
        float4 v = *reinterpret_cast<const float4*>(base + (size_t)row * W_ + col4 * 4);
        acc += (v.x + v.y) + (v.z + v.w);
    }
#pragma unroll
    for (int off = 16; off > 0; off >>= 1)
        acc += __shfl_down_sync(0xFFFFFFFFu, acc, off);

    if (lane == 0)
        g_pooled[b * GC_ + ij * C_ + c] = acc * (1.0f / 4096.0f);
}

// ---------------------------------------------------------------------------
// Kernel 2: MLP. One block per batch element, 256 threads = 8 warps.
// Stage 1: s[256] = mish(pooled @ reduce_w^T + reduce_b), warp-per-output GEMV
// Stage 2: g[1024] = sigmoid(s @ expand_w^T + expand_b)
// ---------------------------------------------------------------------------
__device__ __forceinline__ float mishf(float x) {
    float sp = (x > 20.0f) ? x : log1pf(__expf(x));
    return x * tanhf(sp);
}
__device__ __forceinline__ float sigmoidf_(float x) {
    return 1.0f / (1.0f + __expf(-x));
}

__global__ void __launch_bounds__(256) se4_mlp(const float* __restrict__ reduce_w,
                                               const float* __restrict__ reduce_b,
                                               const float* __restrict__ expand_w,
                                               const float* __restrict__ expand_b) {
    __shared__ float sm_pooled[GC_];   // 1024
    __shared__ float sm_s[SQ_];        // 256

    int b    = blockIdx.x;
    int tid  = threadIdx.x;
    int warp = tid >> 5;
    int lane = tid & 31;

    for (int k = tid; k < GC_; k += 256)
        sm_pooled[k] = g_pooled[b * GC_ + k];
    __syncthreads();

    const float4* pooled4 = reinterpret_cast<const float4*>(sm_pooled);

    // Stage 1: 256 outputs, 8 warps -> 32 rounds
    for (int rnd = 0; rnd < 32; ++rnd) {
        int out = rnd * 8 + warp;
        const float4* wrow = reinterpret_cast<const float4*>(reduce_w + (size_t)out * GC_);
        float acc = 0.0f;
#pragma unroll
        for (int k4 = lane; k4 < GC_ / 4; k4 += 32) {
            float4 wv = wrow[k4];
            float4 pv = pooled4[k4];
            acc += wv.x * pv.x + wv.y * pv.y + wv.z * pv.z + wv.w * pv.w;
        }
#pragma unroll
        for (int off = 16; off > 0; off >>= 1)
            acc += __shfl_down_sync(0xFFFFFFFFu, acc, off);
        if (lane == 0)
            sm_s[out] = mishf(acc + reduce_b[out]);
    }
    __syncthreads();

    const float4* s4 = reinterpret_cast<const float4*>(sm_s);

    // Stage 2: 1024 outputs, 8 warps -> 128 rounds; k-dim = 256 = 64 float4
    for (int rnd = 0; rnd < 128; ++rnd) {
        int out = rnd * 8 + warp;
        const float4* wrow = reinterpret_cast<const float4*>(expand_w + (size_t)out * SQ_);
        float acc = 0.0f;
#pragma unroll
        for (int k4 = lane; k4 < SQ_ / 4; k4 += 32) {
            float4 wv = wrow[k4];
            float4 sv = s4[k4];
            acc += wv.x * sv.x + wv.y * sv.y + wv.z * sv.z + wv.w * sv.w;
        }
#pragma unroll
        for (int off = 16; off > 0; off >>= 1)
            acc += __shfl_down_sync(0xFFFFFFFFu, acc, off);
        if (lane == 0)
            g_gates[b * GC_ + out] = sigmoidf_(acc + expand_b[out]);
    }
}

// ---------------------------------------------------------------------------
// Kernel 3: gating. One float4 per thread. 8.39M float4 total.
// ---------------------------------------------------------------------------
__global__ void __launch_bounds__(256) se4_gate(const float* __restrict__ t,
                                                float* __restrict__ out) {
    size_t idx4 = (size_t)blockIdx.x * blockDim.x + threadIdx.x;
    // total float4 = 8*64*256*64 = 8388608; grid sized exactly
    int w4 = (int)(idx4 & 63);         // 64 float4 per row
    size_t rest = idx4 >> 6;
    int h = (int)(rest & 255);
    size_t rest2 = rest >> 8;
    int c = (int)(rest2 & 63);
    int b = (int)(rest2 >> 6);

    int i = h >> 6;
    int j = w4 >> 4;                   // (w4*4)/64
    float gate = __ldg(&g_gates[b * GC_ + (i * 4 + j) * C_ + c]);

    float4 v = *reinterpret_cast<const float4*>(t + idx4 * 4);
    v.x *= gate; v.y *= gate; v.z *= gate; v.w *= gate;
    *reinterpret_cast<float4*>(out + idx4 * 4) = v;
}

// ---------------------------------------------------------------------------
extern "C" void kernel_launch(void* const* d_in, const int* in_sizes, int n_in,
                              void* d_out, int out_size) {
    const float* t        = (const float*)d_in[0];
    const float* reduce_w = (const float*)d_in[1];
    const float* reduce_b = (const float*)d_in[2];
    const float* expand_w = (const float*)d_in[3];
    const float* expand_b = (const float*)d_in[4];
    float* out = (float*)d_out;

    // Kernel 1: 8192 warps = 1024 blocks x 256 threads
    se4_pool<<<1024, 256>>>(t);
    // Kernel 2: one block per batch element
    se4_mlp<<<B_, 256>>>(reduce_w, reduce_b, expand_w, expand_b);
    // Kernel 3: 8388608 float4 / 256 = 32768 blocks
    se4_gate<<<32768, 256>>>(t, out);
}

// round 2
// speedup vs baseline: 2.7897x; 2.7897x over previous
#include <cuda_runtime.h>
#include <math.h>

// ---------------------------------------------------------------------------
// SE4: 4x4-patch squeeze-excite
//   t: [B=8, C=64, H=256, W=256] fp32
//   pooled[b, (i*4+j)*64 + c] = mean of 64x64 patch (i,j) of channel c
//   s = mish(pooled @ reduce_w^T + reduce_b)   [8,256]
//   g = sigmoid(s @ expand_w^T + expand_b)     [8,1024]
//   out[b,c,h,w] = t[b,c,h,w] * g[b, (h/64*4 + w/64)*64 + c]
// ---------------------------------------------------------------------------

#define B_   8
#define C_   64
#define H_   256
#define W_   256
#define SQ_  256
#define GC_  (16 * C_)          // 1024
#define NPOOL (B_ * GC_)        // 8192

__device__ float g_pooled[NPOOL];
__device__ float g_s[B_ * SQ_];
__device__ float g_gates[NPOOL];

// ---------------------------------------------------------------------------
// Kernel 1: patch mean pool. One warp per (b, c, i, j). 8192 warps total.
// ---------------------------------------------------------------------------
__global__ void __launch_bounds__(256) se4_pool(const float* __restrict__ t) {
    int warp = (blockIdx.x * blockDim.x + threadIdx.x) >> 5;
    int lane = threadIdx.x & 31;
    if (warp >= NPOOL) return;

    int b  = warp >> 10;            // / 1024
    int r  = warp & 1023;
    int c  = r >> 4;                // / 16
    int ij = r & 15;
    int i  = ij >> 2;
    int j  = ij & 3;

    const float* base = t + (((size_t)(b * C_ + c) * H_ + i * 64) * W_ + j * 64);
    int row0 = lane >> 4;           // 0 or 1
    int col4 = lane & 15;           // 0..15

    float acc = 0.0f;
#pragma unroll 8
    for (int it = 0; it < 32; ++it) {
        int row = it * 2 + row0;
        float4 v = *reinterpret_cast<const float4*>(base + (size_t)row * W_ + col4 * 4);
        acc += (v.x + v.y) + (v.z + v.w);
    }
#pragma unroll
    for (int off = 16; off > 0; off >>= 1)
        acc += __shfl_down_sync(0xFFFFFFFFu, acc, off);

    if (lane == 0)
        g_pooled[b * GC_ + ij * C_ + c] = acc * (1.0f / 4096.0f);
}

// ---------------------------------------------------------------------------
// Activations
// ---------------------------------------------------------------------------
__device__ __forceinline__ float mishf(float x) {
    float sp = (x > 20.0f) ? x : log1pf(__expf(x));
    return x * tanhf(sp);
}
__device__ __forceinline__ float sigmoidf_(float x) {
    return 1.0f / (1.0f + __expf(-x));
}

// ---------------------------------------------------------------------------
// Kernel 2a: s[b,out] = mish(dot(pooled[b,:], reduce_w[out,:]) + reduce_b[out])
// One warp per (b,out): 8*256 = 2048 warps = 256 blocks x 256 threads.
// Dot length 1024 = 256 float4 -> 8 float4 per lane.
// ---------------------------------------------------------------------------
__global__ void __launch_bounds__(256) se4_mlp1(const float* __restrict__ reduce_w,
                                                const float* __restrict__ reduce_b) {
    int warp = (blockIdx.x * blockDim.x + threadIdx.x) >> 5;
    int lane = threadIdx.x & 31;
    if (warp >= B_ * SQ_) return;
    int b   = warp >> 8;            // / 256
    int out = warp & 255;

    const float4* wrow = reinterpret_cast<const float4*>(reduce_w + (size_t)out * GC_);
    const float4* prow = reinterpret_cast<const float4*>(g_pooled + (size_t)b * GC_);

    float acc = 0.0f;
#pragma unroll
    for (int k4 = lane; k4 < GC_ / 4; k4 += 32) {
        float4 wv = wrow[k4];
        float4 pv = prow[k4];
        acc += wv.x * pv.x + wv.y * pv.y + wv.z * pv.z + wv.w * pv.w;
    }
#pragma unroll
    for (int off = 16; off > 0; off >>= 1)
        acc += __shfl_down_sync(0xFFFFFFFFu, acc, off);
    if (lane == 0)
        g_s[b * SQ_ + out] = mishf(acc + reduce_b[out]);
}

// ---------------------------------------------------------------------------
// Kernel 2b: g[b,out] = sigmoid(dot(s[b,:], expand_w[out,:]) + expand_b[out])
// One warp per (b,out): 8*1024 = 8192 warps = 1024 blocks x 256 threads.
// Dot length 256 = 64 float4 -> 2 float4 per lane.
// ---------------------------------------------------------------------------
__global__ void __launch_bounds__(256) se4_mlp2(const float* __restrict__ expand_w,
                                                const float* __restrict__ expand_b) {
    int warp = (blockIdx.x * blockDim.x + threadIdx.x) >> 5;
    int lane = threadIdx.x & 31;
    if (warp >= B_ * GC_) return;
    int b   = warp >> 10;           // / 1024
    int out = warp & 1023;

    const float4* wrow = reinterpret_cast<const float4*>(expand_w + (size_t)out * SQ_);
    const float4* srow = reinterpret_cast<const float4*>(g_s + (size_t)b * SQ_);

    float acc = 0.0f;
#pragma unroll
    for (int k4 = lane; k4 < SQ_ / 4; k4 += 32) {
        float4 wv = wrow[k4];
        float4 sv = srow[k4];
        acc += wv.x * sv.x + wv.y * sv.y + wv.z * sv.z + wv.w * sv.w;
    }
#pragma unroll
    for (int off = 16; off > 0; off >>= 1)
        acc += __shfl_down_sync(0xFFFFFFFFu, acc, off);
    if (lane == 0)
        g_gates[b * GC_ + out] = sigmoidf_(acc + expand_b[out]);
}

// ---------------------------------------------------------------------------
// Kernel 3: gating. One float4 per thread. 8.39M float4 total.
// ---------------------------------------------------------------------------
__global__ void __launch_bounds__(256) se4_gate(const float* __restrict__ t,
                                                float* __restrict__ out) {
    size_t idx4 = (size_t)blockIdx.x * blockDim.x + threadIdx.x;
    int w4 = (int)(idx4 & 63);         // 64 float4 per row
    size_t rest = idx4 >> 6;
    int h = (int)(rest & 255);
    size_t rest2 = rest >> 8;
    int c = (int)(rest2 & 63);
    int b = (int)(rest2 >> 6);

    int i = h >> 6;
    int j = w4 >> 4;                   // (w4*4)/64
    float gate = __ldg(&g_gates[b * GC_ + (i * 4 + j) * C_ + c]);

    float4 v = *reinterpret_cast<const float4*>(t + idx4 * 4);
    v.x *= gate; v.y *= gate; v.z *= gate; v.w *= gate;
    *reinterpret_cast<float4*>(out + idx4 * 4) = v;
}

// ---------------------------------------------------------------------------
extern "C" void kernel_launch(void* const* d_in, const int* in_sizes, int n_in,
                              void* d_out, int out_size) {
    const float* t        = (const float*)d_in[0];
    const float* reduce_w = (const float*)d_in[1];
    const float* reduce_b = (const float*)d_in[2];
    const float* expand_w = (const float*)d_in[3];
    const float* expand_b = (const float*)d_in[4];
    float* out = (float*)d_out;

    se4_pool<<<1024, 256>>>(t);
    se4_mlp1<<<256, 256>>>(reduce_w, reduce_b);
    se4_mlp2<<<1024, 256>>>(expand_w, expand_b);
    se4_gate<<<32768, 256>>>(t, out);
}

// round 3
// speedup vs baseline: 2.8736x; 1.0301x over previous
#include <cuda_runtime.h>
#include <math.h>

// ---------------------------------------------------------------------------
// SE4: 4x4-patch squeeze-excite
//   t: [B=8, C=64, H=256, W=256] fp32
//   pooled[b, (i*4+j)*64 + c] = mean of 64x64 patch (i,j) of channel c
//   s = mish(pooled @ reduce_w^T + reduce_b)   [8,256]
//   g = sigmoid(s @ expand_w^T + expand_b)     [8,1024]
//   out[b,c,h,w] = t[b,c,h,w] * g[b, (h/64*4 + w/64)*64 + c]
// ---------------------------------------------------------------------------

#define B_   8
#define C_   64
#define H_   256
#define W_   256
#define SQ_  256
#define GC_  (16 * C_)          // 1024
#define NPOOL (B_ * GC_)        // 8192

__device__ float g_pooled[NPOOL];
__device__ float g_s[B_ * SQ_];
__device__ float g_gates[NPOOL];

// ---------------------------------------------------------------------------
// Kernel 1: patch mean pool. One warp per (b, c, i, j). 8192 warps.
// 4 independent accumulators -> deeper MLP. Reads cached (L2 reuse by gate).
// ---------------------------------------------------------------------------
__global__ void __launch_bounds__(256) se4_pool(const float* __restrict__ t) {
    int warp = (blockIdx.x * blockDim.x + threadIdx.x) >> 5;
    int lane = threadIdx.x & 31;
    if (warp >= NPOOL) return;

    int b  = warp >> 10;            // / 1024
    int r  = warp & 1023;
    int c  = r >> 4;                // / 16
    int ij = r & 15;
    int i  = ij >> 2;
    int j  = ij & 3;

    const float* base = t + (((size_t)(b * C_ + c) * H_ + i * 64) * W_ + j * 64);
    int row0 = lane >> 4;           // 0 or 1
    int col4 = lane & 15;           // 0..15
    const float* p = base + (size_t)row0 * W_ + col4 * 4;

    float a0 = 0.f, a1 = 0.f, a2 = 0.f, a3 = 0.f;
#pragma unroll
    for (int it = 0; it < 8; ++it) {
        float4 v0 = *reinterpret_cast<const float4*>(p + (size_t)(it * 8 + 0) * W_);
        float4 v1 = *reinterpret_cast<const float4*>(p + (size_t)(it * 8 + 2) * W_);
        float4 v2 = *reinterpret_cast<const float4*>(p + (size_t)(it * 8 + 4) * W_);
        float4 v3 = *reinterpret_cast<const float4*>(p + (size_t)(it * 8 + 6) * W_);
        a0 += (v0.x + v0.y) + (v0.z + v0.w);
        a1 += (v1.x + v1.y) + (v1.z + v1.w);
        a2 += (v2.x + v2.y) + (v2.z + v2.w);
        a3 += (v3.x + v3.y) + (v3.z + v3.w);
    }
    float acc = (a0 + a1) + (a2 + a3);
#pragma unroll
    for (int off = 16; off > 0; off >>= 1)
        acc += __shfl_down_sync(0xFFFFFFFFu, acc, off);

    if (lane == 0)
        g_pooled[b * GC_ + ij * C_ + c] = acc * (1.0f / 4096.0f);
}

// ---------------------------------------------------------------------------
// Activations
// ---------------------------------------------------------------------------
__device__ __forceinline__ float mishf(float x) {
    float sp = (x > 20.0f) ? x : log1pf(__expf(x));
    return x * tanhf(sp);
}
__device__ __forceinline__ float sigmoidf_(float x) {
    return 1.0f / (1.0f + __expf(-x));
}

// ---------------------------------------------------------------------------
// Kernel 2a: s = mish(pooled @ reduce_w^T + b). One warp per (b,out).
// ---------------------------------------------------------------------------
__global__ void __launch_bounds__(256) se4_mlp1(const float* __restrict__ reduce_w,
                                                const float* __restrict__ reduce_b) {
    int warp = (blockIdx.x * blockDim.x + threadIdx.x) >> 5;
    int lane = threadIdx.x & 31;
    if (warp >= B_ * SQ_) return;
    int b   = warp >> 8;
    int out = warp & 255;

    const float4* wrow = reinterpret_cast<const float4*>(reduce_w + (size_t)out * GC_);
    const float4* prow = reinterpret_cast<const float4*>(g_pooled + (size_t)b * GC_);

    float acc = 0.0f;
#pragma unroll
    for (int k4 = lane; k4 < GC_ / 4; k4 += 32) {
        float4 wv = wrow[k4];
        float4 pv = prow[k4];
        acc += wv.x * pv.x + wv.y * pv.y + wv.z * pv.z + wv.w * pv.w;
    }
#pragma unroll
    for (int off = 16; off > 0; off >>= 1)
        acc += __shfl_down_sync(0xFFFFFFFFu, acc, off);
    if (lane == 0)
        g_s[b * SQ_ + out] = mishf(acc + reduce_b[out]);
}

// ---------------------------------------------------------------------------
// Kernel 2b: g = sigmoid(s @ expand_w^T + b). One warp per (b,out).
// ---------------------------------------------------------------------------
__global__ void __launch_bounds__(256) se4_mlp2(const float* __restrict__ expand_w,
                                                const float* __restrict__ expand_b) {
    int warp = (blockIdx.x * blockDim.x + threadIdx.x) >> 5;
    int lane = threadIdx.x & 31;
    if (warp >= B_ * GC_) return;
    int b   = warp >> 10;
    int out = warp & 1023;

    const float4* wrow = reinterpret_cast<const float4*>(expand_w + (size_t)out * SQ_);
    const float4* srow = reinterpret_cast<const float4*>(g_s + (size_t)b * SQ_);

    float acc = 0.0f;
#pragma unroll
    for (int k4 = lane; k4 < SQ_ / 4; k4 += 32) {
        float4 wv = wrow[k4];
        float4 sv = srow[k4];
        acc += wv.x * sv.x + wv.y * sv.y + wv.z * sv.z + wv.w * sv.w;
    }
#pragma unroll
    for (int off = 16; off > 0; off >>= 1)
        acc += __shfl_down_sync(0xFFFFFFFFu, acc, off);
    if (lane == 0)
        g_gates[b * GC_ + out] = sigmoidf_(acc + expand_b[out]);
}

// ---------------------------------------------------------------------------
// Kernel 3: gating. One float4 per thread, blocks in REVERSE address order
// (tail of t is still L2-resident from the pool pass). Streaming hints:
// t is dead after use (.cs load), out should not thrash L2 (.cs store).
// ---------------------------------------------------------------------------
__global__ void __launch_bounds__(256) se4_gate(const float* __restrict__ t,
                                                float* __restrict__ out) {
    int bid = gridDim.x - 1 - blockIdx.x;          // reverse block order
    size_t idx4 = (size_t)bid * blockDim.x + threadIdx.x;

    int w4 = (int)(idx4 & 63);         // 64 float4 per row
    size_t rest = idx4 >> 6;
    int h = (int)(rest & 255);
    size_t rest2 = rest >> 8;
    int c = (int)(rest2 & 63);
    int b = (int)(rest2 >> 6);

    int i = h >> 6;
    int j = w4 >> 4;                   // (w4*4)/64
    float gate = __ldg(&g_gates[b * GC_ + (i * 4 + j) * C_ + c]);

    float4 v = __ldcs(reinterpret_cast<const float4*>(t) + idx4);
    v.x *= gate; v.y *= gate; v.z *= gate; v.w *= gate;
    __stcs(reinterpret_cast<float4*>(out) + idx4, v);
}

// ---------------------------------------------------------------------------
extern "C" void kernel_launch(void* const* d_in, const int* in_sizes, int n_in,
                              void* d_out, int out_size) {
    const float* t        = (const float*)d_in[0];
    const float* reduce_w = (const float*)d_in[1];
    const float* reduce_b = (const float*)d_in[2];
    const float* expand_w = (const float*)d_in[3];
    const float* expand_b = (const float*)d_in[4];
    float* out = (float*)d_out;

    se4_pool<<<1024, 256>>>(t);
    se4_mlp1<<<256, 256>>>(reduce_w, reduce_b);
    se4_mlp2<<<1024, 256>>>(expand_w, expand_b);
    se4_gate<<<32768, 256>>>(t, out);
}